// round 15
// baseline (speedup 1.0000x reference)
#include <cuda_runtime.h>
#include <cuda_fp16.h>
#include <cstdint>

// Problem shapes (fixed)
#define B_  8
#define C_  64
#define N_  2000
#define T_  12
#define E_  64000
#define HID_ 32

// Scratch
__device__ float g_M1[C_ * C_];            // M1[cin*64 + cout]
__device__ float g_M2[C_ * C_];
__device__ __half2 g_lr[B_ * C_ * N_];     // packed (lt, rt) per (b,c,n)
// fp16 tables, flat layout [b][n][64c]; float4 units: row stride 8.
__device__ __half g_Ah[B_ * N_ * C_];      // includes conv_b
__device__ __half g_Bh[B_ * N_ * C_];

__device__ __forceinline__ unsigned pack_half2(float a, float b) {
    __half2 h = __floats2half2_rn(a, b);
    return *reinterpret_cast<unsigned*>(&h);
}

// ---------------------------------------------------------------------------
// Kernel 1: fold. M1[cin][cout] = s1*sum_h W3[cin,h]*cw[cout,h];
//                 M2[cin][cout] = s2*sum_h W4[cin,h]*cw[cout,32+h].
// ---------------------------------------------------------------------------
__global__ __launch_bounds__(128) void fold_kernel(const float* __restrict__ W3,
                                                   const float* __restrict__ W4,
                                                   const float* __restrict__ cw,
                                                   const float* __restrict__ s1p,
                                                   const float* __restrict__ s2p) {
    const int cin = blockIdx.x;
    const int t = threadIdx.x;
    const int mat = t >> 6;
    const int cout = t & 63;

    const float* wrow = mat ? (W4 + cin * HID_) : (W3 + cin * HID_);
    const float sc = mat ? __ldg(s2p) : __ldg(s1p);
    const float4* cwp = reinterpret_cast<const float4*>(cw + cout * 64 + mat * 32);
    const float4* wp = reinterpret_cast<const float4*>(wrow);

    float acc = 0.f;
#pragma unroll
    for (int q = 0; q < 8; q++) {
        float4 w = __ldg(wp + q);
        float4 c = __ldg(cwp + q);
        acc = fmaf(w.x, c.x, acc);
        acc = fmaf(w.y, c.y, acc);
        acc = fmaf(w.z, c.z, acc);
        acc = fmaf(w.w, c.w, acc);
    }
    (mat ? g_M2 : g_M1)[cin * 64 + cout] = acc * sc;
}

// ---------------------------------------------------------------------------
// Kernel 2: time reduction, pure streaming; packed half2 output.
// Grid (8 n-chunks, 64 c, 8 b) x 256 threads.
// ---------------------------------------------------------------------------
__global__ __launch_bounds__(256) void reduce_kernel(const float* __restrict__ x) {
    const int n = blockIdx.x * 256 + threadIdx.x;
    const int c = blockIdx.y;
    const int b = blockIdx.z;
    if (n >= N_) return;

    const float4* px = reinterpret_cast<const float4*>(
        x + ((size_t)(b * C_ + c) * N_ + n) * T_);
    float4 v0 = __ldg(px), v1 = __ldg(px + 1), v2 = __ldg(px + 2);
    float xv[12] = {v0.x, v0.y, v0.z, v0.w,
                    v1.x, v1.y, v1.z, v1.w,
                    v2.x, v2.y, v2.z, v2.w};
    float lt = 0.f, s = 0.f;
#pragma unroll
    for (int t = 0; t < T_; t++) {
        lt = fmaf(xv[t], (float)t * (1.0f / 11.0f), lt);
        s += xv[t];
    }
    g_lr[(size_t)(b * C_ + c) * N_ + n] = __floats2half2_rn(lt, s - lt);
}

// ---------------------------------------------------------------------------
// Kernel 3: project (R12 form, half2 lr input).
// A[b,n,:] = lt[b,:,n]@M1 + cb; Bv = rt[b,:,n]@M2 -> fp16 tables.
// Grid (32 n-tiles, 8 b) x 256 threads, 64 KB dynamic smem.
// ---------------------------------------------------------------------------
__global__ __launch_bounds__(256) void project_kernel(const float* __restrict__ conv_b) {
    extern __shared__ float4 sm[];
    float4* sM1  = sm;            // [c][co4]  64*16 = 1024 f4 (16 KB)
    float4* sM2  = sm + 1024;     // 16 KB
    float4* slt4 = sm + 2048;     // [c][n4]   16 KB
    float4* srt4 = sm + 3072;     // 16 KB
    float* sltf = reinterpret_cast<float*>(slt4);
    float* srtf = reinterpret_cast<float*>(srt4);

    const int tid = threadIdx.x;
    const int b = blockIdx.y;
    const int n0 = blockIdx.x * 64;

    {
        const float4* m1g = reinterpret_cast<const float4*>(g_M1);
        const float4* m2g = reinterpret_cast<const float4*>(g_M2);
#pragma unroll
        for (int k = 0; k < 4; k++) {
            int i = tid + 256 * k;
            sM1[i] = m1g[i];
            sM2[i] = m2g[i];
        }
    }

#pragma unroll
    for (int k = 0; k < 16; k++) {
        int i = tid + 256 * k;
        int c = i >> 6;
        int nl = i & 63;
        int n = n0 + nl;
        float lv = 0.f, rv = 0.f;
        if (n < N_) {
            float2 f = __half22float2(g_lr[(size_t)(b * C_ + c) * N_ + n]);
            lv = f.x; rv = f.y;
        }
        sltf[i] = lv;
        srtf[i] = rv;
    }
    __syncthreads();

    const int cg = tid & 15;          // co4 group
    const int ng = tid >> 4;          // n4 group

    float4 a0 = {0,0,0,0}, a1 = {0,0,0,0}, a2 = {0,0,0,0}, a3 = {0,0,0,0};
    float4 b0 = {0,0,0,0}, b1 = {0,0,0,0}, b2 = {0,0,0,0}, b3 = {0,0,0,0};

#pragma unroll 16
    for (int c = 0; c < 64; c++) {
        float4 m1 = sM1[c * 16 + cg];
        float4 m2 = sM2[c * 16 + cg];
        float4 l = slt4[c * 16 + ng];
        float4 r = srt4[c * 16 + ng];

        a0.x = fmaf(l.x, m1.x, a0.x); a0.y = fmaf(l.x, m1.y, a0.y);
        a0.z = fmaf(l.x, m1.z, a0.z); a0.w = fmaf(l.x, m1.w, a0.w);
        a1.x = fmaf(l.y, m1.x, a1.x); a1.y = fmaf(l.y, m1.y, a1.y);
        a1.z = fmaf(l.y, m1.z, a1.z); a1.w = fmaf(l.y, m1.w, a1.w);
        a2.x = fmaf(l.z, m1.x, a2.x); a2.y = fmaf(l.z, m1.y, a2.y);
        a2.z = fmaf(l.z, m1.z, a2.z); a2.w = fmaf(l.z, m1.w, a2.w);
        a3.x = fmaf(l.w, m1.x, a3.x); a3.y = fmaf(l.w, m1.y, a3.y);
        a3.z = fmaf(l.w, m1.z, a3.z); a3.w = fmaf(l.w, m1.w, a3.w);

        b0.x = fmaf(r.x, m2.x, b0.x); b0.y = fmaf(r.x, m2.y, b0.y);
        b0.z = fmaf(r.x, m2.z, b0.z); b0.w = fmaf(r.x, m2.w, b0.w);
        b1.x = fmaf(r.y, m2.x, b1.x); b1.y = fmaf(r.y, m2.y, b1.y);
        b1.z = fmaf(r.y, m2.z, b1.z); b1.w = fmaf(r.y, m2.w, b1.w);
        b2.x = fmaf(r.z, m2.x, b2.x); b2.y = fmaf(r.z, m2.y, b2.y);
        b2.z = fmaf(r.z, m2.z, b2.z); b2.w = fmaf(r.z, m2.w, b2.w);
        b3.x = fmaf(r.w, m2.x, b3.x); b3.y = fmaf(r.w, m2.y, b3.y);
        b3.z = fmaf(r.w, m2.z, b3.z); b3.w = fmaf(r.w, m2.w, b3.w);
    }

    float4 cbv = reinterpret_cast<const float4*>(conv_b)[cg];
    uint2* gA2 = reinterpret_cast<uint2*>(g_Ah);
    uint2* gB2 = reinterpret_cast<uint2*>(g_Bh);

    float4 av[4] = {a0, a1, a2, a3};
    float4 bv[4] = {b0, b1, b2, b3};
#pragma unroll
    for (int i = 0; i < 4; i++) {
        int n = n0 + ng * 4 + i;
        if (n < N_) {
            size_t o = ((size_t)b * N_ + n) * 16 + cg;
            float4 aa = av[i];
            aa.x += cbv.x; aa.y += cbv.y; aa.z += cbv.z; aa.w += cbv.w;
            uint2 ua, ub;
            ua.x = pack_half2(aa.x, aa.y);
            ua.y = pack_half2(aa.z, aa.w);
            ub.x = pack_half2(bv[i].x, bv[i].y);
            ub.y = pack_half2(bv[i].z, bv[i].w);
            gA2[o] = ua;
            gB2[o] = ub;
        }
    }
}

// ---------------------------------------------------------------------------
// Kernel 4: gather v3 = R10 geometry (8 thr/edge, full-row float4 loads:
// 1 read-wavefront/edge/table) x R11 ILP (2 edges/thread: 4 gathered
// LDG.128 in flight). ~2 warp-inst/edge.
// Grid (E/64, B) x 256 threads = 8000 blocks.
// ---------------------------------------------------------------------------
__global__ __launch_bounds__(256) void gather_add_kernel(const int* __restrict__ idx,
                                                         const int* __restrict__ idy,
                                                         float4* __restrict__ out) {
    const int tid = threadIdx.x;
    const int b = blockIdx.y;
    const int el = tid >> 3;          // 0..31
    const int q = tid & 7;            // float4 within the 128B row
    const int e0 = blockIdx.x * 64 + el;
    const int e1 = e0 + 32;

    const int n1a = __ldg(idx + e0);
    const int n1b = __ldg(idx + e1);
    const int n2a = __ldg(idy + e0);
    const int n2b = __ldg(idy + e1);

    const float4* __restrict__ A4 = reinterpret_cast<const float4*>(g_Ah);
    const float4* __restrict__ B4 = reinterpret_cast<const float4*>(g_Bh);

    float4 ua0 = __ldg(A4 + ((size_t)b * N_ + n1a) * 8 + q);
    float4 ub0 = __ldg(B4 + ((size_t)b * N_ + n2a) * 8 + q);
    float4 ua1 = __ldg(A4 + ((size_t)b * N_ + n1b) * 8 + q);
    float4 ub1 = __ldg(B4 + ((size_t)b * N_ + n2b) * 8 + q);

    {
        const __half2* ha = reinterpret_cast<const __half2*>(&ua0);
        const __half2* hb = reinterpret_cast<const __half2*>(&ub0);
        float2 p0a = __half22float2(ha[0]), p0b = __half22float2(hb[0]);
        float2 p1a = __half22float2(ha[1]), p1b = __half22float2(hb[1]);
        float2 p2a = __half22float2(ha[2]), p2b = __half22float2(hb[2]);
        float2 p3a = __half22float2(ha[3]), p3b = __half22float2(hb[3]);
        size_t o = ((size_t)b * E_ + e0) * 16 + q * 2;
        out[o]     = make_float4(p0a.x + p0b.x, p0a.y + p0b.y, p1a.x + p1b.x, p1a.y + p1b.y);
        out[o + 1] = make_float4(p2a.x + p2b.x, p2a.y + p2b.y, p3a.x + p3b.x, p3a.y + p3b.y);
    }
    {
        const __half2* ha = reinterpret_cast<const __half2*>(&ua1);
        const __half2* hb = reinterpret_cast<const __half2*>(&ub1);
        float2 p0a = __half22float2(ha[0]), p0b = __half22float2(hb[0]);
        float2 p1a = __half22float2(ha[1]), p1b = __half22float2(hb[1]);
        float2 p2a = __half22float2(ha[2]), p2b = __half22float2(hb[2]);
        float2 p3a = __half22float2(ha[3]), p3b = __half22float2(hb[3]);
        size_t o = ((size_t)b * E_ + e1) * 16 + q * 2;
        out[o]     = make_float4(p0a.x + p0b.x, p0a.y + p0b.y, p1a.x + p1b.x, p1a.y + p1b.y);
        out[o + 1] = make_float4(p2a.x + p2b.x, p2a.y + p2b.y, p3a.x + p3b.x, p3a.y + p3b.y);
    }
}

// ---------------------------------------------------------------------------
// Launch. Inputs: x, idx, idy, W1_scale, W2_scale, W3, W4, conv_w, conv_b
// ---------------------------------------------------------------------------
extern "C" void kernel_launch(void* const* d_in, const int* in_sizes, int n_in,
                              void* d_out, int out_size) {
    const float* x   = (const float*)d_in[0];
    const int* idx   = (const int*)d_in[1];
    const int* idy   = (const int*)d_in[2];
    const float* s1  = (const float*)d_in[3];
    const float* s2  = (const float*)d_in[4];
    const float* W3  = (const float*)d_in[5];
    const float* W4  = (const float*)d_in[6];
    const float* cw  = (const float*)d_in[7];
    const float* cb  = (const float*)d_in[8];
    float4* out = (float4*)d_out;

    fold_kernel<<<64, 128>>>(W3, W4, cw, s1, s2);

    dim3 grdR(8, 64, 8);
    reduce_kernel<<<grdR, 256>>>(x);

    const int smem_bytes = 4096 * sizeof(float4);   // 64 KB
    cudaFuncSetAttribute(project_kernel,
                         cudaFuncAttributeMaxDynamicSharedMemorySize, smem_bytes);
    dim3 grdP(32, 8);
    project_kernel<<<grdP, 256, smem_bytes>>>(cb);

    dim3 grdG(E_ / 64, B_);           // (1000, 8) = 8000 blocks
    gather_add_kernel<<<grdG, 256>>>(idx, idy, out);
}

// round 16
// speedup vs baseline: 1.2292x; 1.2292x over previous
#include <cuda_runtime.h>
#include <cuda_fp16.h>
#include <cstdint>

// Problem shapes (fixed)
#define B_  8
#define C_  64
#define N_  2000
#define T_  12
#define E_  64000
#define HID_ 32

// Scratch
__device__ float g_M1[C_ * C_];            // M1[cin*64 + cout]
__device__ float g_M2[C_ * C_];
__device__ __half2 g_lr[B_ * C_ * N_];     // packed (lt, rt) per (b,c,n)
// fp16 tables, flat layout [b][n][64c]; uint2 units: row stride 16.
__device__ __half g_Ah[B_ * N_ * C_];      // includes conv_b
__device__ __half g_Bh[B_ * N_ * C_];

__device__ __forceinline__ unsigned pack_half2(float a, float b) {
    __half2 h = __floats2half2_rn(a, b);
    return *reinterpret_cast<unsigned*>(&h);
}

// ---------------------------------------------------------------------------
// Kernel 1: fold. M1[cin][cout] = s1*sum_h W3[cin,h]*cw[cout,h];
//                 M2[cin][cout] = s2*sum_h W4[cin,h]*cw[cout,32+h].
// Grid 64 x 128 threads.
// ---------------------------------------------------------------------------
__global__ __launch_bounds__(128) void fold_kernel(const float* __restrict__ W3,
                                                   const float* __restrict__ W4,
                                                   const float* __restrict__ cw,
                                                   const float* __restrict__ s1p,
                                                   const float* __restrict__ s2p) {
    const int cin = blockIdx.x;
    const int t = threadIdx.x;
    const int mat = t >> 6;
    const int cout = t & 63;

    const float* wrow = mat ? (W4 + cin * HID_) : (W3 + cin * HID_);
    const float sc = mat ? __ldg(s2p) : __ldg(s1p);
    const float4* cwp = reinterpret_cast<const float4*>(cw + cout * 64 + mat * 32);
    const float4* wp = reinterpret_cast<const float4*>(wrow);

    float acc = 0.f;
#pragma unroll
    for (int q = 0; q < 8; q++) {
        float4 w = __ldg(wp + q);
        float4 c = __ldg(cwp + q);
        acc = fmaf(w.x, c.x, acc);
        acc = fmaf(w.y, c.y, acc);
        acc = fmaf(w.z, c.z, acc);
        acc = fmaf(w.w, c.w, acc);
    }
    (mat ? g_M2 : g_M1)[cin * 64 + cout] = acc * sc;
}

// ---------------------------------------------------------------------------
// Kernel 2: time reduction, pure streaming (R12 form); packed half2 output.
// Grid (8 n-chunks, 64 c, 8 b) x 256 threads.
// ---------------------------------------------------------------------------
__global__ __launch_bounds__(256) void reduce_kernel(const float* __restrict__ x) {
    const int n = blockIdx.x * 256 + threadIdx.x;
    const int c = blockIdx.y;
    const int b = blockIdx.z;
    if (n >= N_) return;

    const float4* px = reinterpret_cast<const float4*>(
        x + ((size_t)(b * C_ + c) * N_ + n) * T_);
    float4 v0 = __ldg(px), v1 = __ldg(px + 1), v2 = __ldg(px + 2);
    float xv[12] = {v0.x, v0.y, v0.z, v0.w,
                    v1.x, v1.y, v1.z, v1.w,
                    v2.x, v2.y, v2.z, v2.w};
    float lt = 0.f, s = 0.f;
#pragma unroll
    for (int t = 0; t < T_; t++) {
        lt = fmaf(xv[t], (float)t * (1.0f / 11.0f), lt);
        s += xv[t];
    }
    g_lr[(size_t)(b * C_ + c) * N_ + n] = __floats2half2_rn(lt, s - lt);
}

// ---------------------------------------------------------------------------
// Kernel 3: project (R12 form, half2 lr input).
// A[b,n,:] = lt[b,:,n]@M1 + cb; Bv = rt[b,:,n]@M2 -> fp16 tables.
// Grid (32 n-tiles, 8 b) x 256 threads, 64 KB dynamic smem.
// ---------------------------------------------------------------------------
__global__ __launch_bounds__(256) void project_kernel(const float* __restrict__ conv_b) {
    extern __shared__ float4 sm[];
    float4* sM1  = sm;            // [c][co4]  64*16 = 1024 f4 (16 KB)
    float4* sM2  = sm + 1024;     // 16 KB
    float4* slt4 = sm + 2048;     // [c][n4]   16 KB
    float4* srt4 = sm + 3072;     // 16 KB
    float* sltf = reinterpret_cast<float*>(slt4);
    float* srtf = reinterpret_cast<float*>(srt4);

    const int tid = threadIdx.x;
    const int b = blockIdx.y;
    const int n0 = blockIdx.x * 64;

    {
        const float4* m1g = reinterpret_cast<const float4*>(g_M1);
        const float4* m2g = reinterpret_cast<const float4*>(g_M2);
#pragma unroll
        for (int k = 0; k < 4; k++) {
            int i = tid + 256 * k;
            sM1[i] = m1g[i];
            sM2[i] = m2g[i];
        }
    }

#pragma unroll
    for (int k = 0; k < 16; k++) {
        int i = tid + 256 * k;
        int c = i >> 6;
        int nl = i & 63;
        int n = n0 + nl;
        float lv = 0.f, rv = 0.f;
        if (n < N_) {
            float2 f = __half22float2(g_lr[(size_t)(b * C_ + c) * N_ + n]);
            lv = f.x; rv = f.y;
        }
        sltf[i] = lv;
        srtf[i] = rv;
    }
    __syncthreads();

    const int cg = tid & 15;          // co4 group
    const int ng = tid >> 4;          // n4 group

    float4 a0 = {0,0,0,0}, a1 = {0,0,0,0}, a2 = {0,0,0,0}, a3 = {0,0,0,0};
    float4 b0 = {0,0,0,0}, b1 = {0,0,0,0}, b2 = {0,0,0,0}, b3 = {0,0,0,0};

#pragma unroll 16
    for (int c = 0; c < 64; c++) {
        float4 m1 = sM1[c * 16 + cg];
        float4 m2 = sM2[c * 16 + cg];
        float4 l = slt4[c * 16 + ng];
        float4 r = srt4[c * 16 + ng];

        a0.x = fmaf(l.x, m1.x, a0.x); a0.y = fmaf(l.x, m1.y, a0.y);
        a0.z = fmaf(l.x, m1.z, a0.z); a0.w = fmaf(l.x, m1.w, a0.w);
        a1.x = fmaf(l.y, m1.x, a1.x); a1.y = fmaf(l.y, m1.y, a1.y);
        a1.z = fmaf(l.y, m1.z, a1.z); a1.w = fmaf(l.y, m1.w, a1.w);
        a2.x = fmaf(l.z, m1.x, a2.x); a2.y = fmaf(l.z, m1.y, a2.y);
        a2.z = fmaf(l.z, m1.z, a2.z); a2.w = fmaf(l.z, m1.w, a2.w);
        a3.x = fmaf(l.w, m1.x, a3.x); a3.y = fmaf(l.w, m1.y, a3.y);
        a3.z = fmaf(l.w, m1.z, a3.z); a3.w = fmaf(l.w, m1.w, a3.w);

        b0.x = fmaf(r.x, m2.x, b0.x); b0.y = fmaf(r.x, m2.y, b0.y);
        b0.z = fmaf(r.x, m2.z, b0.z); b0.w = fmaf(r.x, m2.w, b0.w);
        b1.x = fmaf(r.y, m2.x, b1.x); b1.y = fmaf(r.y, m2.y, b1.y);
        b1.z = fmaf(r.y, m2.z, b1.z); b1.w = fmaf(r.y, m2.w, b1.w);
        b2.x = fmaf(r.z, m2.x, b2.x); b2.y = fmaf(r.z, m2.y, b2.y);
        b2.z = fmaf(r.z, m2.z, b2.z); b2.w = fmaf(r.z, m2.w, b2.w);
        b3.x = fmaf(r.w, m2.x, b3.x); b3.y = fmaf(r.w, m2.y, b3.y);
        b3.z = fmaf(r.w, m2.z, b3.z); b3.w = fmaf(r.w, m2.w, b3.w);
    }

    float4 cbv = reinterpret_cast<const float4*>(conv_b)[cg];
    uint2* gA2 = reinterpret_cast<uint2*>(g_Ah);
    uint2* gB2 = reinterpret_cast<uint2*>(g_Bh);

    float4 av[4] = {a0, a1, a2, a3};
    float4 bv[4] = {b0, b1, b2, b3};
#pragma unroll
    for (int i = 0; i < 4; i++) {
        int n = n0 + ng * 4 + i;
        if (n < N_) {
            size_t o = ((size_t)b * N_ + n) * 16 + cg;
            float4 aa = av[i];
            aa.x += cbv.x; aa.y += cbv.y; aa.z += cbv.z; aa.w += cbv.w;
            uint2 ua, ub;
            ua.x = pack_half2(aa.x, aa.y);
            ua.y = pack_half2(aa.z, aa.w);
            ub.x = pack_half2(bv[i].x, bv[i].y);
            ub.y = pack_half2(bv[i].z, bv[i].w);
            gA2[o] = ua;
            gB2[o] = ub;
        }
    }
}

// ---------------------------------------------------------------------------
// Kernel 4: gather (R11 exact — converged optimum, 26.8us).
// Grid (E/64, 2 chalf, B), 256 threads; 8 thr/edge, uint2 loads, 2-edge ILP.
// ---------------------------------------------------------------------------
__global__ __launch_bounds__(256) void gather_add_kernel(const int* __restrict__ idx,
                                                         const int* __restrict__ idy,
                                                         float4* __restrict__ out) {
    const int tid = threadIdx.x;
    const int chalf = blockIdx.y;     // 0..1
    const int b = blockIdx.z;         // 0..7
    const int el = tid >> 3;          // 0..31
    const int q = tid & 7;            // uint2 within 64B half-row
    const int cq = chalf * 8 + q;
    const int e0 = blockIdx.x * 64 + el;
    const int e1 = e0 + 32;

    const int n1a = __ldg(idx + e0);
    const int n1b = __ldg(idx + e1);
    const int n2a = __ldg(idy + e0);
    const int n2b = __ldg(idy + e1);

    const uint2* __restrict__ A2 = reinterpret_cast<const uint2*>(g_Ah);
    const uint2* __restrict__ B2 = reinterpret_cast<const uint2*>(g_Bh);

    uint2 ua0 = __ldg(A2 + ((size_t)b * N_ + n1a) * 16 + cq);
    uint2 ub0 = __ldg(B2 + ((size_t)b * N_ + n2a) * 16 + cq);
    uint2 ua1 = __ldg(A2 + ((size_t)b * N_ + n1b) * 16 + cq);
    uint2 ub1 = __ldg(B2 + ((size_t)b * N_ + n2b) * 16 + cq);

    float2 a00 = __half22float2(*reinterpret_cast<__half2*>(&ua0.x));
    float2 a01 = __half22float2(*reinterpret_cast<__half2*>(&ua0.y));
    float2 v00 = __half22float2(*reinterpret_cast<__half2*>(&ub0.x));
    float2 v01 = __half22float2(*reinterpret_cast<__half2*>(&ub0.y));
    float2 a10 = __half22float2(*reinterpret_cast<__half2*>(&ua1.x));
    float2 a11 = __half22float2(*reinterpret_cast<__half2*>(&ua1.y));
    float2 v10 = __half22float2(*reinterpret_cast<__half2*>(&ub1.x));
    float2 v11 = __half22float2(*reinterpret_cast<__half2*>(&ub1.y));

    out[((size_t)b * E_ + e0) * 16 + cq] =
        make_float4(a00.x + v00.x, a00.y + v00.y, a01.x + v01.x, a01.y + v01.y);
    out[((size_t)b * E_ + e1) * 16 + cq] =
        make_float4(a10.x + v10.x, a10.y + v10.y, a11.x + v11.x, a11.y + v11.y);
}

// ---------------------------------------------------------------------------
// Launch. Inputs: x, idx, idy, W1_scale, W2_scale, W3, W4, conv_w, conv_b
// ---------------------------------------------------------------------------
extern "C" void kernel_launch(void* const* d_in, const int* in_sizes, int n_in,
                              void* d_out, int out_size) {
    const float* x   = (const float*)d_in[0];
    const int* idx   = (const int*)d_in[1];
    const int* idy   = (const int*)d_in[2];
    const float* s1  = (const float*)d_in[3];
    const float* s2  = (const float*)d_in[4];
    const float* W3  = (const float*)d_in[5];
    const float* W4  = (const float*)d_in[6];
    const float* cw  = (const float*)d_in[7];
    const float* cb  = (const float*)d_in[8];
    float4* out = (float4*)d_out;

    fold_kernel<<<64, 128>>>(W3, W4, cw, s1, s2);

    dim3 grdR(8, 64, 8);
    reduce_kernel<<<grdR, 256>>>(x);

    const int smem_bytes = 4096 * sizeof(float4);   // 64 KB
    cudaFuncSetAttribute(project_kernel,
                         cudaFuncAttributeMaxDynamicSharedMemorySize, smem_bytes);
    dim3 grdP(32, 8);
    project_kernel<<<grdP, 256, smem_bytes>>>(cb);

    dim3 grdG(E_ / 64, 2, B_);        // (1000, 2, 8) = 16000 blocks
    gather_add_kernel<<<grdG, 256>>>(idx, idy, out);
}